// round 2
// baseline (speedup 1.0000x reference)
#include <cuda_runtime.h>

#define HID   100
#define G4    400
#define SEQ   8192
#define NCLS  20
#define TB    16
#define NT    800      // lstm threads: 25 warps, 2 threads per gate-row
#define PADH  104      // padded h length (26 x 16B chunks)

// scratch for x_proj (no cudaMalloc allowed)
__device__ float g_xp[SEQ * G4];

__device__ __forceinline__ unsigned long long ffma2(unsigned long long a,
                                                    unsigned long long b,
                                                    unsigned long long c) {
    unsigned long long d;
    asm("fma.rn.f32x2 %0, %1, %2, %3;" : "=l"(d) : "l"(a), "l"(b), "l"(c));
    return d;
}
__device__ __forceinline__ void unpack2(unsigned long long v, float& lo, float& hi) {
    asm("mov.b64 {%0, %1}, %2;" : "=f"(lo), "=f"(hi) : "l"(v));
}
__device__ __forceinline__ unsigned long long pack2(float lo, float hi) {
    unsigned long long v;
    asm("mov.b64 %0, {%1, %2};" : "=l"(v) : "f"(lo), "f"(hi));
    return v;
}
__device__ __forceinline__ float sig_f(float x) {
    return __fdividef(1.f, 1.f + __expf(-x));
}
__device__ __forceinline__ float tanh_f(float x) {
    return __fdividef(2.f, 1.f + __expf(-2.f * x)) - 1.f;
}

// ---------------------------------------------------------------------------
// Kernel 1: embedding gather + x_proj GEMM (+ both biases folded in)
// ---------------------------------------------------------------------------
__global__ void __launch_bounds__(G4, 1)
proj_kernel(const int* __restrict__ seq, const float* __restrict__ emb,
            const float* __restrict__ W_ih, const float* __restrict__ b_ih,
            const float* __restrict__ b_hh) {
    __shared__ float es[TB * HID];
    __shared__ int   sid[TB];
    const int tid = threadIdx.x;
    const int t0  = blockIdx.x * TB;

    if (tid < TB) sid[tid] = seq[t0 + tid];
    __syncthreads();
    for (int n = tid; n < TB * HID; n += G4) {
        int tt = n / HID, k = n % HID;
        es[n] = emb[(long long)sid[tt] * HID + k];
    }
    __syncthreads();

    float acc[TB];
#pragma unroll
    for (int tt = 0; tt < TB; tt++) acc[tt] = 0.f;

    const float* wr = W_ih + tid * HID;
#pragma unroll 4
    for (int k = 0; k < HID; k++) {
        float w = __ldg(&wr[k]);
#pragma unroll
        for (int tt = 0; tt < TB; tt++) acc[tt] += w * es[tt * HID + k];
    }
    float b = b_ih[tid] + b_hh[tid];
#pragma unroll
    for (int tt = 0; tt < TB; tt++)
        g_xp[(t0 + tt) * G4 + tid] = acc[tt] + b;
}

// ---------------------------------------------------------------------------
// Kernel 2: LSTM recurrence, single persistent CTA, 800 threads.
//
// Lane layout (within each of 25 warps): lane = g*8 + jj*2 + half
//   g    = gate (0:i 1:f 2:g 3:o)
//   jj   = row-within-warp (warp w owns hidden rows j = 4w+jj)
//   half = which half of the 104-float padded dot product this thread does
// half h owns 16B chunks {2m+h : m=0..12} of the row -> per LDS.128 the warp
// touches two adjacent 16B regions (same 128B line, disjoint banks) = 1 wf.
// Cross-half sum via shfl_xor(1); gate collection via 4 shfls; ONE barrier
// per step; h double-buffered in smem so writers never race readers.
// ---------------------------------------------------------------------------
__global__ void __launch_bounds__(NT, 1)
lstm_kernel(const float* __restrict__ W_hh,
            const float* __restrict__ fc_w, const float* __restrict__ fc_b,
            float* __restrict__ out) {
    __shared__ __align__(16) float hbuf[2][PADH];
    const int tid  = threadIdx.x;
    const int w    = tid >> 5;
    const int lane = tid & 31;
    const int g    = lane >> 3;
    const int jj   = (lane >> 1) & 3;
    const int half = lane & 1;
    const int j    = w * 4 + jj;        // hidden index 0..99
    const int r    = g * HID + j;       // gate row 0..399

    // Preload this thread's 13 16-byte weight chunks (52 floats = 26 f32x2)
    unsigned long long w2[26];
#pragma unroll
    for (int m = 0; m < 13; m++) {
        const int cidx = 2 * m + half;          // chunk 0..25
        float4 v = make_float4(0.f, 0.f, 0.f, 0.f);
        if (cidx < 25)                          // chunk 25 is zero padding
            v = *(const float4*)(W_hh + r * HID + 4 * cidx);
        w2[2 * m]     = pack2(v.x, v.y);
        w2[2 * m + 1] = pack2(v.z, v.w);
    }

    // zero both h buffers (incl. padding)
    for (int n = tid; n < 2 * PADH; n += NT) ((float*)hbuf)[n] = 0.f;
    float c = 0.f;
    __syncthreads();

    float xv = __ldg(&g_xp[r]);   // t = 0
    for (int t = 0; t < SEQ; t++) {
        // prefetch next step's x_proj (wraps harmlessly at the end)
        float xv_nxt = __ldg(&g_xp[((t + 1) & (SEQ - 1)) * G4 + r]);

        const char* hb = (const char*)hbuf[t & 1];
        unsigned long long acc0 = 0ull, acc1 = 0ull;
#pragma unroll
        for (int m = 0; m < 13; m++) {
            ulonglong2 hv = *(const ulonglong2*)(hb + 32 * m + 16 * half);
            acc0 = ffma2(w2[2 * m],     hv.x, acc0);
            acc1 = ffma2(w2[2 * m + 1], hv.y, acc1);
        }
        float a0, a1, b0, b1;
        unpack2(acc0, a0, a1);
        unpack2(acc1, b0, b1);
        float s = (a0 + b0) + (a1 + b1);
        s += __shfl_xor_sync(0xffffffffu, s, 1);   // combine halves
        float pre = s + xv;

        // activations: rows [200,300) (g==2) are tanh, others sigmoid
        float a = (g == 2) ? tanh_f(pre) : sig_f(pre);

        // collect the 4 gates for row j (base = jj*2+half; lanes base+8k)
        const int base = lane & 7;
        float ai = __shfl_sync(0xffffffffu, a, base);
        float af = __shfl_sync(0xffffffffu, a, base + 8);
        float ag = __shfl_sync(0xffffffffu, a, base + 16);
        float ao = __shfl_sync(0xffffffffu, a, base + 24);

        c = af * c + ai * ag;
        float hn = ao * tanh_f(c);
        hbuf[(t + 1) & 1][j] = hn;   // 8 lanes/row write identical value

        __syncthreads();
        xv = xv_nxt;
    }

    // final FC on h_last (lives in hbuf[0] since SEQ is even)
    if (tid < NCLS) {
        float sfc = fc_b[tid];
        const float* fw = fc_w + tid * HID;
        const float* hl = hbuf[SEQ & 1];
#pragma unroll 4
        for (int k = 0; k < HID; k++) sfc += fw[k] * hl[k];
        out[tid] = sfc;
    }
}

// ---------------------------------------------------------------------------
extern "C" void kernel_launch(void* const* d_in, const int* in_sizes, int n_in,
                              void* d_out, int out_size) {
    const int*   seq  = (const int*)d_in[0];
    const float* emb  = (const float*)d_in[1];
    const float* W_ih = (const float*)d_in[2];
    const float* W_hh = (const float*)d_in[3];
    const float* b_ih = (const float*)d_in[4];
    const float* b_hh = (const float*)d_in[5];
    const float* fc_w = (const float*)d_in[6];
    const float* fc_b = (const float*)d_in[7];
    float* out = (float*)d_out;

    proj_kernel<<<SEQ / TB, G4>>>(seq, emb, W_ih, b_ih, b_hh);
    lstm_kernel<<<1, NT>>>(W_hh, fc_w, fc_b, out);
}

// round 3
// speedup vs baseline: 1.0581x; 1.0581x over previous
#include <cuda_runtime.h>

#define HID   100
#define G4    400
#define SEQ   8192
#define NCLS  20
#define TB    16

// scratch for x_proj (no cudaMalloc allowed)
__device__ float g_xp[SEQ * G4];

__device__ __forceinline__ unsigned long long ffma2(unsigned long long a,
                                                    unsigned long long b,
                                                    unsigned long long c) {
    unsigned long long d;
    asm("fma.rn.f32x2 %0, %1, %2, %3;" : "=l"(d) : "l"(a), "l"(b), "l"(c));
    return d;
}
__device__ __forceinline__ unsigned long long addf2(unsigned long long a,
                                                    unsigned long long b) {
    unsigned long long d;
    asm("add.rn.f32x2 %0, %1, %2;" : "=l"(d) : "l"(a), "l"(b));
    return d;
}
__device__ __forceinline__ void unpack2(unsigned long long v, float& lo, float& hi) {
    asm("mov.b64 {%0, %1}, %2;" : "=f"(lo), "=f"(hi) : "l"(v));
}
__device__ __forceinline__ unsigned long long pack2(float lo, float hi) {
    unsigned long long v;
    asm("mov.b64 %0, {%1, %2};" : "=l"(v) : "f"(lo), "f"(hi));
    return v;
}

// ---------------------------------------------------------------------------
// Kernel 1: embedding gather + x_proj GEMM (+ both biases folded in)
// ---------------------------------------------------------------------------
__global__ void __launch_bounds__(G4, 1)
proj_kernel(const int* __restrict__ seq, const float* __restrict__ emb,
            const float* __restrict__ W_ih, const float* __restrict__ b_ih,
            const float* __restrict__ b_hh) {
    __shared__ float es[TB * HID];
    __shared__ int   sid[TB];
    const int tid = threadIdx.x;
    const int t0  = blockIdx.x * TB;

    if (tid < TB) sid[tid] = seq[t0 + tid];
    __syncthreads();
    for (int n = tid; n < TB * HID; n += G4) {
        int tt = n / HID, k = n % HID;
        es[n] = emb[(long long)sid[tt] * HID + k];
    }
    __syncthreads();

    float acc[TB];
#pragma unroll
    for (int tt = 0; tt < TB; tt++) acc[tt] = 0.f;

    const float4* wr4 = (const float4*)(W_ih + tid * HID);
#pragma unroll 5
    for (int m = 0; m < 25; m++) {
        float4 wv = __ldg(&wr4[m]);
#pragma unroll
        for (int tt = 0; tt < TB; tt++) {
            const float* e = es + tt * HID + 4 * m;
            acc[tt] += wv.x * e[0] + wv.y * e[1] + wv.z * e[2] + wv.w * e[3];
        }
    }
    float b = b_ih[tid] + b_hh[tid];
#pragma unroll
    for (int tt = 0; tt < TB; tt++)
        g_xp[(t0 + tt) * G4 + tid] = acc[tt] + b;
}

// ---------------------------------------------------------------------------
// Kernel 2: LSTM recurrence — single persistent CTA, 400 threads.
// Thread i owns gate-row i of W_hh (100 floats = 50 f32x2 register pairs).
// 4 independent accumulators (13-deep chains instead of 25-deep).
// x_proj prefetched one full step ahead. Unified branch-free activation.
// ---------------------------------------------------------------------------
__global__ void __launch_bounds__(G4, 1)
lstm_kernel(const float* __restrict__ W_hh,
            const float* __restrict__ fc_w, const float* __restrict__ fc_b,
            float* __restrict__ out) {
    __shared__ __align__(16) float h_sh[HID];
    __shared__ float act[G4];
    const int i = threadIdx.x;
    const int gate = i / HID;   // 0:i 1:f 2:g 3:o

    // unified activation constants: a = k1 / (1 + exp2(pre*m2)) + k0
    // sigmoid: 1/(1+e^-x)        -> m2 = -log2(e),  k1 = 1, k0 = 0
    // tanh   : 2/(1+e^-2x) - 1   -> m2 = -2 log2(e), k1 = 2, k0 = -1
    const bool  is_tanh = (gate == 2);
    const float m2 = is_tanh ? -2.885390082f : -1.442695041f;
    const float k1 = is_tanh ? 2.f : 1.f;
    const float k0 = is_tanh ? -1.f : 0.f;

    // preload W_hh row i into register pairs
    unsigned long long w2[50];
    {
        const float2* wr = (const float2*)(W_hh + i * HID);
#pragma unroll
        for (int j = 0; j < 50; j++) {
            float2 t = wr[j];
            w2[j] = pack2(t.x, t.y);
        }
    }

    if (i < HID) h_sh[i] = 0.f;
    float c = 0.f;
    __syncthreads();

    float xv = __ldg(&g_xp[i]);   // t = 0
    for (int t = 0; t < SEQ; t++) {
        // prefetch next step's x_proj (fully hidden under this step)
        float xv_nxt = __ldg(&g_xp[((t + 1) & (SEQ - 1)) * G4 + i]);

        // matvec: 4 independent f32x2 accumulators
        unsigned long long a0 = 0ull, a1 = 0ull, a2 = 0ull, a3 = 0ull;
        const ulonglong2* h2 = (const ulonglong2*)h_sh;
#pragma unroll
        for (int m = 0; m < 25; m += 2) {
            ulonglong2 hv = h2[m];          // LDS.128 broadcast
            a0 = ffma2(w2[2 * m],     hv.x, a0);
            a1 = ffma2(w2[2 * m + 1], hv.y, a1);
            if (m + 1 < 25) {
                ulonglong2 hw = h2[m + 1];
                a2 = ffma2(w2[2 * m + 2], hw.x, a2);
                a3 = ffma2(w2[2 * m + 3], hw.y, a3);
            }
        }
        a0 = addf2(a0, a2);
        a1 = addf2(a1, a3);
        a0 = addf2(a0, a1);
        float lo, hi;
        unpack2(a0, lo, hi);
        float pre = (lo + hi) + xv;

        // branch-free activation (exact EX2/RCP path)
        float e = exp2f(pre * m2);          // FMUL + MUFU.EX2
        float a = __fdividef(k1, 1.f + e) + k0;
        act[i] = a;
        __syncthreads();

        if (i < HID) {
            float ig = act[i];
            float fg = act[i + HID];
            float gg = act[i + 2 * HID];
            float og = act[i + 3 * HID];
            c = fg * c + ig * gg;
            // h = o * tanh(c), exact path
            float ec = exp2f(c * -2.885390082f);
            h_sh[i] = __fdividef(2.f * og, 1.f + ec) - og;
        }
        __syncthreads();
        xv = xv_nxt;
    }

    // final FC: out[j] = h_last . fc_w[j] + fc_b[j]
    if (i < NCLS) {
        float s = fc_b[i];
        const float* fw = fc_w + i * HID;
#pragma unroll 4
        for (int k = 0; k < HID; k++) s += fw[k] * h_sh[k];
        out[i] = s;
    }
}

// ---------------------------------------------------------------------------
extern "C" void kernel_launch(void* const* d_in, const int* in_sizes, int n_in,
                              void* d_out, int out_size) {
    const int*   seq  = (const int*)d_in[0];
    const float* emb  = (const float*)d_in[1];
    const float* W_ih = (const float*)d_in[2];
    const float* W_hh = (const float*)d_in[3];
    const float* b_ih = (const float*)d_in[4];
    const float* b_hh = (const float*)d_in[5];
    const float* fc_w = (const float*)d_in[6];
    const float* fc_b = (const float*)d_in[7];
    float* out = (float*)d_out;

    proj_kernel<<<SEQ / TB, G4>>>(seq, emb, W_ih, b_ih, b_hh);
    lstm_kernel<<<1, G4>>>(W_hh, fc_w, fc_b, out);
}